// round 1
// baseline (speedup 1.0000x reference)
#include <cuda_runtime.h>
#include <math.h>

// Problem constants (fixed shapes for this problem instance)
#define BZ 4
#define SZ 2048
#define DD 768
#define HH 3072
#define EE 8
#define KK 2
#define NTOK (BZ*SZ)        // 8192 tokens
#define NENT (NTOK*KK)      // 16384 routing entries
#define CAP 1536            // capacity = (B*S/E)*1.5

// -------- scratch (static device globals; no allocation at runtime) --------
__device__ int   g_topi[NENT];
__device__ float g_topp[NENT];
__device__ int   g_exp_tok[EE*CAP];
__device__ float g_exp_w[EE*CAP];
__device__ int   g_cnt[EE];
__device__ float g_hidden[(size_t)EE*CAP*HH];   // 8*1536*3072 fp32 = 151 MB

// ============================================================
// Kernel 1: router — one warp per token.
// logits = x @ Wr ; softmax ; top-2 ; renormalize by top-2 sum.
// ============================================================
__global__ void router_kernel(const float* __restrict__ x,
                              const float* __restrict__ Wr)
{
    int warp_id = (blockIdx.x * blockDim.x + threadIdx.x) >> 5;
    int lane = threadIdx.x & 31;
    if (warp_id >= NTOK) return;

    const float* xr = x + (size_t)warp_id * DD;
    float xv[DD/32];
    #pragma unroll
    for (int i = 0; i < DD/32; i++) xv[i] = xr[lane + i*32];

    float logit[EE];
    #pragma unroll
    for (int e = 0; e < EE; e++) {
        float s = 0.f;
        #pragma unroll
        for (int i = 0; i < DD/32; i++)
            s += xv[i] * Wr[(size_t)(lane + i*32)*EE + e];
        #pragma unroll
        for (int off = 16; off; off >>= 1)
            s += __shfl_xor_sync(0xffffffffu, s, off);
        logit[e] = s;   // full sum in every lane (butterfly)
    }

    if (lane == 0) {
        float mx = logit[0];
        #pragma unroll
        for (int e = 1; e < EE; e++) mx = fmaxf(mx, logit[e]);
        float pe[EE]; float se = 0.f;
        #pragma unroll
        for (int e = 0; e < EE; e++) { pe[e] = expf(logit[e]-mx); se += pe[e]; }
        float inv = 1.f/se;
        #pragma unroll
        for (int e = 0; e < EE; e++) pe[e] *= inv;
        // top-2 (strict > keeps lowest index on ties, matching lax.top_k)
        int i1 = 0;
        #pragma unroll
        for (int e = 1; e < EE; e++) if (pe[e] > pe[i1]) i1 = e;
        int i2 = (i1 == 0) ? 1 : 0;
        #pragma unroll
        for (int e = 0; e < EE; e++) if (e != i1 && pe[e] > pe[i2]) i2 = e;
        float s12 = pe[i1] + pe[i2];
        g_topi[warp_id*2+0] = i1;  g_topp[warp_id*2+0] = pe[i1]/s12;
        g_topi[warp_id*2+1] = i2;  g_topp[warp_id*2+1] = pe[i2]/s12;
    }
}

// ============================================================
// Kernel 2: capacity-limited assignment.
// Entry n kept iff (# earlier entries in flat (b,s,k) order with same
// expert) < CAP. Single block; exact sequential semantics via
// intra-warp match ranks + cross-warp scan + running per-expert base.
// ============================================================
__global__ void capacity_kernel()
{
    __shared__ int base[EE];
    __shared__ int warp_cnt[32][EE];

    int tid  = threadIdx.x;
    int warp = tid >> 5;
    int lane = tid & 31;
    if (tid < EE) base[tid] = 0;
    __syncthreads();

    for (int chunk = 0; chunk < NENT/1024; chunk++) {
        int n = chunk*1024 + tid;
        int e = g_topi[n];
        float p = g_topp[n];

        unsigned mask = __match_any_sync(0xffffffffu, e);
        int rank   = __popc(mask & ((1u << lane) - 1u));
        int leader = __ffs(mask) - 1;

        if (lane < EE) warp_cnt[warp][lane] = 0;
        __syncwarp();
        if (lane == leader) warp_cnt[warp][e] = __popc(mask);
        __syncthreads();

        int prefix = 0;
        for (int w = 0; w < warp; w++) prefix += warp_cnt[w][e];
        int pos = base[e] + prefix + rank;
        if (pos < CAP) {
            g_exp_tok[e*CAP + pos] = n >> 1;   // token index
            g_exp_w  [e*CAP + pos] = p;
        }
        __syncthreads();
        if (tid < EE) {
            int tot = 0;
            for (int w = 0; w < 32; w++) tot += warp_cnt[w][tid];
            base[tid] += tot;
        }
        __syncthreads();
    }
    if (tid < EE) g_cnt[tid] = min(base[tid], CAP);
}

// ============================================================
// GEMM tiling constants (fp32 SIMT baseline)
// ============================================================
#define BM 64
#define BN 64
#define BK 16

// Kernel 3: hidden[e,m,:] = gelu( x[tok_m,:] @ w1[e] + b1[e] )
// grid: (HH/BN, CAP/BM, EE), 256 threads
__global__ void gemm1_kernel(const float* __restrict__ x,
                             const float* __restrict__ w1,
                             const float* __restrict__ b1)
{
    int e = blockIdx.z;
    int cnt = g_cnt[e];
    int m0 = blockIdx.y * BM;
    if (m0 >= cnt) return;
    int n0 = blockIdx.x * BN;
    const float* w1e = w1 + (size_t)e * DD * HH;

    __shared__ float As[BK][BM];
    __shared__ float Bs[BK][BN];

    int tid = threadIdx.x;
    int arow = tid >> 2;             // 0..63
    int acol = (tid & 3) * 4;        // 0,4,8,12
    int brow = tid >> 4;             // 0..15
    int bcol = (tid & 15) * 4;       // 0..60
    int tx = tid & 15, ty = tid >> 4;

    int tok_a = -1;
    if (m0 + arow < cnt) tok_a = g_exp_tok[e*CAP + m0 + arow];

    float acc[4][4] = {};

    for (int k0 = 0; k0 < DD; k0 += BK) {
        float4 av = make_float4(0.f,0.f,0.f,0.f);
        if (tok_a >= 0)
            av = *(const float4*)(x + (size_t)tok_a * DD + k0 + acol);
        As[acol+0][arow] = av.x; As[acol+1][arow] = av.y;
        As[acol+2][arow] = av.z; As[acol+3][arow] = av.w;

        *(float4*)&Bs[brow][bcol] =
            *(const float4*)(w1e + (size_t)(k0 + brow)*HH + n0 + bcol);
        __syncthreads();

        #pragma unroll
        for (int kk = 0; kk < BK; kk++) {
            float4 a = *(const float4*)&As[kk][ty*4];
            float4 b = *(const float4*)&Bs[kk][tx*4];
            float ar[4] = {a.x,a.y,a.z,a.w};
            float br[4] = {b.x,b.y,b.z,b.w};
            #pragma unroll
            for (int i = 0; i < 4; i++)
                #pragma unroll
                for (int j = 0; j < 4; j++)
                    acc[i][j] += ar[i]*br[j];
        }
        __syncthreads();
    }

    float* He = g_hidden + (size_t)e * CAP * HH;
    const float* b1e = b1 + (size_t)e * HH;
    #pragma unroll
    for (int i = 0; i < 4; i++) {
        int m = m0 + ty*4 + i;
        if (m < cnt) {
            #pragma unroll
            for (int j = 0; j < 4; j++) {
                int n = n0 + tx*4 + j;
                float v = acc[i][j] + b1e[n];
                He[(size_t)m*HH + n] = 0.5f*v*(1.0f + erff(v*0.70710678118654752f));
            }
        }
    }
}

// Kernel 4: y = hidden[e] @ w2[e] + b2[e];  out[tok,:] += w * y  (atomic)
// grid: (DD/BN, CAP/BM, EE), 256 threads
__global__ void gemm2_kernel(const float* __restrict__ w2,
                             const float* __restrict__ b2,
                             float* __restrict__ out)
{
    int e = blockIdx.z;
    int cnt = g_cnt[e];
    int m0 = blockIdx.y * BM;
    if (m0 >= cnt) return;
    int n0 = blockIdx.x * BN;
    const float* w2e = w2 + (size_t)e * HH * DD;
    const float* He  = g_hidden + (size_t)e * CAP * HH;

    __shared__ float As[BK][BM];
    __shared__ float Bs[BK][BN];

    int tid = threadIdx.x;
    int arow = tid >> 2;
    int acol = (tid & 3) * 4;
    int brow = tid >> 4;
    int bcol = (tid & 15) * 4;
    int tx = tid & 15, ty = tid >> 4;

    bool arow_ok = (m0 + arow < cnt);

    float acc[4][4] = {};

    for (int k0 = 0; k0 < HH; k0 += BK) {
        float4 av = make_float4(0.f,0.f,0.f,0.f);
        if (arow_ok)
            av = *(const float4*)(He + (size_t)(m0 + arow)*HH + k0 + acol);
        As[acol+0][arow] = av.x; As[acol+1][arow] = av.y;
        As[acol+2][arow] = av.z; As[acol+3][arow] = av.w;

        *(float4*)&Bs[brow][bcol] =
            *(const float4*)(w2e + (size_t)(k0 + brow)*DD + n0 + bcol);
        __syncthreads();

        #pragma unroll
        for (int kk = 0; kk < BK; kk++) {
            float4 a = *(const float4*)&As[kk][ty*4];
            float4 b = *(const float4*)&Bs[kk][tx*4];
            float ar[4] = {a.x,a.y,a.z,a.w};
            float br[4] = {b.x,b.y,b.z,b.w};
            #pragma unroll
            for (int i = 0; i < 4; i++)
                #pragma unroll
                for (int j = 0; j < 4; j++)
                    acc[i][j] += ar[i]*br[j];
        }
        __syncthreads();
    }

    const float* b2e = b2 + (size_t)e * DD;
    #pragma unroll
    for (int i = 0; i < 4; i++) {
        int m = m0 + ty*4 + i;
        if (m < cnt) {
            int tok = g_exp_tok[e*CAP + m];
            float w = g_exp_w[e*CAP + m];
            #pragma unroll
            for (int j = 0; j < 4; j++) {
                int n = n0 + tx*4 + j;
                float y = acc[i][j] + b2e[n];
                atomicAdd(&out[(size_t)tok*DD + n], w*y);
            }
        }
    }
}

// ============================================================
// Launch
// ============================================================
extern "C" void kernel_launch(void* const* d_in, const int* in_sizes, int n_in,
                              void* d_out, int out_size)
{
    const float* x  = (const float*)d_in[0];
    const float* Wr = (const float*)d_in[1];
    const float* w1 = (const float*)d_in[2];
    const float* b1 = (const float*)d_in[3];
    const float* w2 = (const float*)d_in[4];
    const float* b2 = (const float*)d_in[5];
    float* out = (float*)d_out;

    cudaMemsetAsync(out, 0, (size_t)out_size * sizeof(float));

    router_kernel<<<NTOK/8, 256>>>(x, Wr);           // 8 warps/block
    capacity_kernel<<<1, 1024>>>();
    gemm1_kernel<<<dim3(HH/BN, CAP/BM, EE), 256>>>(x, w1, b1);
    gemm2_kernel<<<dim3(DD/BN, CAP/BM, EE), 256>>>(w2, b2, out);
}

// round 2
// speedup vs baseline: 3.6567x; 3.6567x over previous
#include <cuda_runtime.h>
#include <cstdint>
#include <math.h>

// Problem constants
#define BZ 4
#define SZ 2048
#define DD 768
#define HH 3072
#define EE 8
#define KK 2
#define NTOK (BZ*SZ)
#define NENT (NTOK*KK)
#define CAP 1536

// GEMM tiling
#define BM 128
#define BN 128
#define BK 16
#define APAD 20    // BK+4  (A smem row stride, floats)
#define BPAD 136   // BN+8  (B smem row stride, floats)

// -------- scratch --------
__device__ int   g_topi[NENT];
__device__ float g_topp[NENT];
__device__ int   g_exp_tok[EE*CAP];
__device__ float g_exp_w[EE*CAP];
__device__ int   g_cnt[EE];
__device__ float g_hidden[(size_t)EE*CAP*HH];   // 151 MB fp32

// ---------------- helpers ----------------
__device__ __forceinline__ void cp_async16(uint32_t saddr, const void* gptr, int src_bytes) {
    asm volatile("cp.async.cg.shared.global [%0], [%1], 16, %2;\n"
                 :: "r"(saddr), "l"(gptr), "r"(src_bytes));
}
__device__ __forceinline__ void cp_commit() { asm volatile("cp.async.commit_group;\n"); }
__device__ __forceinline__ void cp_wait1()  { asm volatile("cp.async.wait_group 1;\n"); }
__device__ __forceinline__ void cp_wait0()  { asm volatile("cp.async.wait_group 0;\n"); }

__device__ __forceinline__ uint32_t f2tf32(float v) {
    uint32_t r;
    asm("cvt.rna.tf32.f32 %0, %1;" : "=r"(r) : "f"(v));
    return r;
}

__device__ __forceinline__ void mma_tf32(float c[4],
                                         uint32_t a0, uint32_t a1, uint32_t a2, uint32_t a3,
                                         uint32_t b0, uint32_t b1) {
    asm volatile("mma.sync.aligned.m16n8k8.row.col.f32.tf32.tf32.f32 "
                 "{%0,%1,%2,%3}, {%4,%5,%6,%7}, {%8,%9}, {%0,%1,%2,%3};"
                 : "+f"(c[0]), "+f"(c[1]), "+f"(c[2]), "+f"(c[3])
                 : "r"(a0), "r"(a1), "r"(a2), "r"(a3), "r"(b0), "r"(b1));
}

// ============================================================
// Kernel 1: router — one warp per token.
// ============================================================
__global__ void router_kernel(const float* __restrict__ x,
                              const float* __restrict__ Wr)
{
    int warp_id = (blockIdx.x * blockDim.x + threadIdx.x) >> 5;
    int lane = threadIdx.x & 31;
    if (warp_id >= NTOK) return;

    const float* xr = x + (size_t)warp_id * DD;
    float xv[DD/32];
    #pragma unroll
    for (int i = 0; i < DD/32; i++) xv[i] = xr[lane + i*32];

    float logit[EE];
    #pragma unroll
    for (int e = 0; e < EE; e++) {
        float s = 0.f;
        #pragma unroll
        for (int i = 0; i < DD/32; i++)
            s += xv[i] * Wr[(size_t)(lane + i*32)*EE + e];
        #pragma unroll
        for (int off = 16; off; off >>= 1)
            s += __shfl_xor_sync(0xffffffffu, s, off);
        logit[e] = s;
    }

    if (lane == 0) {
        float mx = logit[0];
        #pragma unroll
        for (int e = 1; e < EE; e++) mx = fmaxf(mx, logit[e]);
        float pe[EE]; float se = 0.f;
        #pragma unroll
        for (int e = 0; e < EE; e++) { pe[e] = expf(logit[e]-mx); se += pe[e]; }
        float inv = 1.f/se;
        #pragma unroll
        for (int e = 0; e < EE; e++) pe[e] *= inv;
        int i1 = 0;
        #pragma unroll
        for (int e = 1; e < EE; e++) if (pe[e] > pe[i1]) i1 = e;
        int i2 = (i1 == 0) ? 1 : 0;
        #pragma unroll
        for (int e = 0; e < EE; e++) if (e != i1 && pe[e] > pe[i2]) i2 = e;
        float s12 = pe[i1] + pe[i2];
        g_topi[warp_id*2+0] = i1;  g_topp[warp_id*2+0] = pe[i1]/s12;
        g_topi[warp_id*2+1] = i2;  g_topp[warp_id*2+1] = pe[i2]/s12;
    }
}

// ============================================================
// Kernel 2: capacity-limited assignment (exact serial semantics).
// ============================================================
__global__ void capacity_kernel()
{
    __shared__ int base[EE];
    __shared__ int warp_cnt[32][EE];

    int tid  = threadIdx.x;
    int warp = tid >> 5;
    int lane = tid & 31;
    if (tid < EE) base[tid] = 0;
    __syncthreads();

    for (int chunk = 0; chunk < NENT/1024; chunk++) {
        int n = chunk*1024 + tid;
        int e = g_topi[n];
        float p = g_topp[n];

        unsigned mask = __match_any_sync(0xffffffffu, e);
        int rank   = __popc(mask & ((1u << lane) - 1u));
        int leader = __ffs(mask) - 1;

        if (lane < EE) warp_cnt[warp][lane] = 0;
        __syncwarp();
        if (lane == leader) warp_cnt[warp][e] = __popc(mask);
        __syncthreads();

        int prefix = 0;
        for (int w = 0; w < warp; w++) prefix += warp_cnt[w][e];
        int pos = base[e] + prefix + rank;
        if (pos < CAP) {
            g_exp_tok[e*CAP + pos] = n >> 1;
            g_exp_w  [e*CAP + pos] = p;
        }
        __syncthreads();
        if (tid < EE) {
            int tot = 0;
            for (int w = 0; w < 32; w++) tot += warp_cnt[w][tid];
            base[tid] += tot;
        }
        __syncthreads();
    }
    if (tid < EE) g_cnt[tid] = min(base[tid], CAP);
}

// ============================================================
// GEMM1 (tf32 tensor cores): hidden = gelu(gather(x) @ w1[e] + b1[e])
// grid (HH/BN, CAP/BM, EE), 256 threads
// ============================================================
__global__ void gemm1_kernel(const float* __restrict__ x,
                             const float* __restrict__ w1,
                             const float* __restrict__ b1)
{
    __shared__ float As[2][BM*APAD];
    __shared__ float Bs[2][BK*BPAD];
    __shared__ int   stok[BM];

    const int e   = blockIdx.z;
    const int cnt = g_cnt[e];
    const int m0  = blockIdx.y * BM;
    if (m0 >= cnt) return;
    const int n0  = blockIdx.x * BN;
    const float* w1e = w1 + (size_t)e * DD * HH;

    const int tid  = threadIdx.x;
    const int warp = tid >> 5;
    const int lane = tid & 31;
    const int g    = lane >> 2;
    const int tq   = lane & 3;
    const int wm   = (warp >> 2) * 64;   // warp m offset (0,64)
    const int wn   = (warp & 3) * 32;    // warp n offset (0,32,64,96)

    // token table for this block
    if (tid < BM) {
        int m = m0 + tid;
        stok[tid] = (m < cnt) ? g_exp_tok[e*CAP + m] : 0;
    }
    __syncthreads();

    // A-load mapping: 2 float4 per thread
    int ar0 = tid >> 2;            // 0..63
    int ar1 = ar0 + 64;
    int ac4 = (tid & 3) * 4;
    const float* aptr0 = x + (size_t)stok[ar0]*DD + ac4;
    const float* aptr1 = x + (size_t)stok[ar1]*DD + ac4;
    int asz0 = (m0 + ar0 < cnt) ? 16 : 0;
    int asz1 = (m0 + ar1 < cnt) ? 16 : 0;

    // B-load mapping: 2 float4 per thread (16 rows x 32 f4-cols)
    int br0 = tid >> 5;            // 0..7
    int br1 = br0 + 8;
    int bc4 = (tid & 31) * 4;
    const float* bptr0 = w1e + (size_t)br0*HH + n0 + bc4;
    const float* bptr1 = w1e + (size_t)br1*HH + n0 + bc4;

    uint32_t sa0[2], sa1[2], sb0[2], sb1[2];
    #pragma unroll
    for (int b = 0; b < 2; b++) {
        sa0[b] = (uint32_t)__cvta_generic_to_shared(&As[b][ar0*APAD + ac4]);
        sa1[b] = (uint32_t)__cvta_generic_to_shared(&As[b][ar1*APAD + ac4]);
        sb0[b] = (uint32_t)__cvta_generic_to_shared(&Bs[b][br0*BPAD + bc4]);
        sb1[b] = (uint32_t)__cvta_generic_to_shared(&Bs[b][br1*BPAD + bc4]);
    }

    float acc[4][4][4] = {};

    const int NIT = DD / BK;
    // prologue: stage 0
    cp_async16(sa0[0], aptr0, asz0);
    cp_async16(sa1[0], aptr1, asz1);
    cp_async16(sb0[0], bptr0, 16);
    cp_async16(sb1[0], bptr1, 16);
    cp_commit();

    for (int it = 0; it < NIT; it++) {
        int buf = it & 1;
        if (it + 1 < NIT) {
            int nb = buf ^ 1;
            int koff = (it+1) * BK;
            cp_async16(sa0[nb], aptr0 + koff, asz0);
            cp_async16(sa1[nb], aptr1 + koff, asz1);
            cp_async16(sb0[nb], bptr0 + (size_t)koff*HH, 16);
            cp_async16(sb1[nb], bptr1 + (size_t)koff*HH, 16);
            cp_commit();
            cp_wait1();
        } else {
            cp_wait0();
        }
        __syncthreads();

        const float* as = As[buf];
        const float* bs = Bs[buf];
        #pragma unroll
        for (int kk = 0; kk < BK; kk += 8) {
            uint32_t af[4][4];
            #pragma unroll
            for (int mi = 0; mi < 4; mi++) {
                int r0 = wm + mi*16 + g;
                af[mi][0] = f2tf32(as[(r0    )*APAD + kk + tq    ]);
                af[mi][1] = f2tf32(as[(r0 + 8)*APAD + kk + tq    ]);
                af[mi][2] = f2tf32(as[(r0    )*APAD + kk + tq + 4]);
                af[mi][3] = f2tf32(as[(r0 + 8)*APAD + kk + tq + 4]);
            }
            uint32_t bf[4][2];
            #pragma unroll
            for (int ni = 0; ni < 4; ni++) {
                int c = wn + ni*8 + g;
                bf[ni][0] = f2tf32(bs[(kk + tq    )*BPAD + c]);
                bf[ni][1] = f2tf32(bs[(kk + tq + 4)*BPAD + c]);
            }
            #pragma unroll
            for (int mi = 0; mi < 4; mi++)
                #pragma unroll
                for (int ni = 0; ni < 4; ni++)
                    mma_tf32(acc[mi][ni], af[mi][0], af[mi][1], af[mi][2], af[mi][3],
                             bf[ni][0], bf[ni][1]);
        }
        __syncthreads();
    }

    // epilogue: bias + exact gelu, store hidden
    float* He = g_hidden + (size_t)e * CAP * HH;
    const float* b1e = b1 + (size_t)e * HH;
    #pragma unroll
    for (int mi = 0; mi < 4; mi++) {
        int r0 = m0 + wm + mi*16 + g;
        #pragma unroll
        for (int half = 0; half < 2; half++) {
            int m = r0 + half*8;
            if (m < cnt) {
                #pragma unroll
                for (int ni = 0; ni < 4; ni++) {
                    int c = n0 + wn + ni*8 + 2*tq;
                    float v0 = acc[mi][ni][half*2+0] + b1e[c];
                    float v1 = acc[mi][ni][half*2+1] + b1e[c+1];
                    He[(size_t)m*HH + c  ] = 0.5f*v0*(1.0f + erff(v0*0.70710678118654752f));
                    He[(size_t)m*HH + c+1] = 0.5f*v1*(1.0f + erff(v1*0.70710678118654752f));
                }
            }
        }
    }
}

// ============================================================
// GEMM2 (tf32): out[tok] += w * (hidden[e] @ w2[e] + b2[e])
// grid (DD/BN, CAP/BM, EE), 256 threads
// ============================================================
__global__ void gemm2_kernel(const float* __restrict__ w2,
                             const float* __restrict__ b2,
                             float* __restrict__ out)
{
    __shared__ float As[2][BM*APAD];
    __shared__ float Bs[2][BK*BPAD];

    const int e   = blockIdx.z;
    const int cnt = g_cnt[e];
    const int m0  = blockIdx.y * BM;
    if (m0 >= cnt) return;
    const int n0  = blockIdx.x * BN;
    const float* w2e = w2 + (size_t)e * HH * DD;
    const float* He  = g_hidden + (size_t)e * CAP * HH;

    const int tid  = threadIdx.x;
    const int warp = tid >> 5;
    const int lane = tid & 31;
    const int g    = lane >> 2;
    const int tq   = lane & 3;
    const int wm   = (warp >> 2) * 64;
    const int wn   = (warp & 3) * 32;

    int ar0 = tid >> 2;
    int ar1 = ar0 + 64;
    int ac4 = (tid & 3) * 4;
    const float* aptr0 = He + (size_t)(m0 + ar0)*HH + ac4;
    const float* aptr1 = He + (size_t)(m0 + ar1)*HH + ac4;
    int asz0 = (m0 + ar0 < cnt) ? 16 : 0;
    int asz1 = (m0 + ar1 < cnt) ? 16 : 0;

    int br0 = tid >> 5;
    int br1 = br0 + 8;
    int bc4 = (tid & 31) * 4;
    const float* bptr0 = w2e + (size_t)br0*DD + n0 + bc4;
    const float* bptr1 = w2e + (size_t)br1*DD + n0 + bc4;

    uint32_t sa0[2], sa1[2], sb0[2], sb1[2];
    #pragma unroll
    for (int b = 0; b < 2; b++) {
        sa0[b] = (uint32_t)__cvta_generic_to_shared(&As[b][ar0*APAD + ac4]);
        sa1[b] = (uint32_t)__cvta_generic_to_shared(&As[b][ar1*APAD + ac4]);
        sb0[b] = (uint32_t)__cvta_generic_to_shared(&Bs[b][br0*BPAD + bc4]);
        sb1[b] = (uint32_t)__cvta_generic_to_shared(&Bs[b][br1*BPAD + bc4]);
    }

    float acc[4][4][4] = {};

    const int NIT = HH / BK;
    cp_async16(sa0[0], aptr0, asz0);
    cp_async16(sa1[0], aptr1, asz1);
    cp_async16(sb0[0], bptr0, 16);
    cp_async16(sb1[0], bptr1, 16);
    cp_commit();

    for (int it = 0; it < NIT; it++) {
        int buf = it & 1;
        if (it + 1 < NIT) {
            int nb = buf ^ 1;
            int koff = (it+1) * BK;
            cp_async16(sa0[nb], aptr0 + koff, asz0);
            cp_async16(sa1[nb], aptr1 + koff, asz1);
            cp_async16(sb0[nb], bptr0 + (size_t)koff*DD, 16);
            cp_async16(sb1[nb], bptr1 + (size_t)koff*DD, 16);
            cp_commit();
            cp_wait1();
        } else {
            cp_wait0();
        }
        __syncthreads();

        const float* as = As[buf];
        const float* bs = Bs[buf];
        #pragma unroll
        for (int kk = 0; kk < BK; kk += 8) {
            uint32_t af[4][4];
            #pragma unroll
            for (int mi = 0; mi < 4; mi++) {
                int r0 = wm + mi*16 + g;
                af[mi][0] = f2tf32(as[(r0    )*APAD + kk + tq    ]);
                af[mi][1] = f2tf32(as[(r0 + 8)*APAD + kk + tq    ]);
                af[mi][2] = f2tf32(as[(r0    )*APAD + kk + tq + 4]);
                af[mi][3] = f2tf32(as[(r0 + 8)*APAD + kk + tq + 4]);
            }
            uint32_t bf[4][2];
            #pragma unroll
            for (int ni = 0; ni < 4; ni++) {
                int c = wn + ni*8 + g;
                bf[ni][0] = f2tf32(bs[(kk + tq    )*BPAD + c]);
                bf[ni][1] = f2tf32(bs[(kk + tq + 4)*BPAD + c]);
            }
            #pragma unroll
            for (int mi = 0; mi < 4; mi++)
                #pragma unroll
                for (int ni = 0; ni < 4; ni++)
                    mma_tf32(acc[mi][ni], af[mi][0], af[mi][1], af[mi][2], af[mi][3],
                             bf[ni][0], bf[ni][1]);
        }
        __syncthreads();
    }

    const float* b2e = b2 + (size_t)e * DD;
    #pragma unroll
    for (int mi = 0; mi < 4; mi++) {
        int r0 = m0 + wm + mi*16 + g;
        #pragma unroll
        for (int half = 0; half < 2; half++) {
            int m = r0 + half*8;
            if (m < cnt) {
                int tok = g_exp_tok[e*CAP + m];
                float w = g_exp_w[e*CAP + m];
                #pragma unroll
                for (int ni = 0; ni < 4; ni++) {
                    int c = n0 + wn + ni*8 + 2*tq;
                    float y0 = acc[mi][ni][half*2+0] + b2e[c];
                    float y1 = acc[mi][ni][half*2+1] + b2e[c+1];
                    atomicAdd(&out[(size_t)tok*DD + c  ], w*y0);
                    atomicAdd(&out[(size_t)tok*DD + c+1], w*y1);
                }
            }
        }
    }
}

// ============================================================
extern "C" void kernel_launch(void* const* d_in, const int* in_sizes, int n_in,
                              void* d_out, int out_size)
{
    const float* x  = (const float*)d_in[0];
    const float* Wr = (const float*)d_in[1];
    const float* w1 = (const float*)d_in[2];
    const float* b1 = (const float*)d_in[3];
    const float* w2 = (const float*)d_in[4];
    const float* b2 = (const float*)d_in[5];
    float* out = (float*)d_out;

    cudaMemsetAsync(out, 0, (size_t)out_size * sizeof(float));

    router_kernel<<<NTOK/8, 256>>>(x, Wr);
    capacity_kernel<<<1, 1024>>>();
    gemm1_kernel<<<dim3(HH/BN, CAP/BM, EE), 256>>>(x, w1, b1);
    gemm2_kernel<<<dim3(DD/BN, CAP/BM, EE), 256>>>(w2, b2, out);
}